// round 12
// baseline (speedup 1.0000x reference)
#include <cuda_runtime.h>
#include <cuda_bf16.h>
#include <cuda_fp16.h>
#include <cstdint>

#define N_NODES 50000
#define N_EDGES 800000
#define HID 128
#define NG 128
#define OUTD 10
#define EPS 1e-5f
#define SCAN_BLOCKS 49

#if defined(__CUDA_ARCH_FEAT_SM103_ALL) || defined(__CUDA_ARCH_FEAT_SM100_ALL) || \
    (defined(__CUDA_ARCH_SPECIFIC__))
#define HAS_TCGEN05 1
#else
#define HAS_TCGEN05 0
#endif

// ---- layer_tc smem layout (byte offsets from 1024-aligned base) ----
#define OFF_TMEM 0
#define OFF_MBAR0 8
#define OFF_MBAR1 16
#define OFF_BIAS 64
#define OFF_GAM  576
#define OFF_BET  1088
#define OFF_WH   2048                  // weight hi tile, blocked-atom, 32KB
#define OFF_WL   (OFF_WH + 32768)      // weight lo tile, 32KB
#define SMEM_USED (OFF_WH + 67584)     // staging (128*33*16B) overlays WH/WL
#define SMEM_TOTAL (SMEM_USED + 1024)  // + alignment slack  (~69.6KB; x2 CTAs fits)
#define BF16_IDESC_N64 0x8100490u
#define TMEM_COLS 256                  // 2 CTAs x 256 = 512 = SM TMEM capacity
#define TM_D  0
#define TM_AH 128
#define TM_AL 192

// -------- device scratch --------
__device__ int   d_is64;
__device__ int   d_deg[N_NODES];
__device__ int   d_rowptr[N_NODES + 1];
__device__ int   d_cursor[N_NODES];
__device__ int   d_bsum[SCAN_BLOCKS];
__device__ int   d_btop[SCAN_BLOCKS];
__device__ int   d_col[N_EDGES];
__device__ __align__(16) float d_wt[4 * HID * HID];   // transposed weights [N][K]
__device__ __align__(16) __half d_xh[N_NODES * HID];  // fp16 gather source
__device__ __align__(16) float d_agg[N_NODES * HID];
__device__ __align__(16) float d_bufA[N_NODES * HID];
__device__ __align__(16) float d_bufB[N_NODES * HID];
__device__ __align__(16) float d_pooled[NG * HID];
__device__ float d_cnt[NG];

__device__ __forceinline__ float warp_sum(float v) {
    #pragma unroll
    for (int o = 16; o > 0; o >>= 1) v += __shfl_xor_sync(0xFFFFFFFFu, v, o);
    return v;
}
__device__ __forceinline__ int load_idx(const void* p, long long i) {
    if (d_is64) return (int)((const long long*)p)[i];
    return ((const int*)p)[i];
}
__device__ __forceinline__ uint32_t smem_u32(const void* p) {
    uint32_t a;
    asm("{ .reg .u64 t; cvta.to.shared.u64 t, %1; cvt.u32.u64 %0, t; }" : "=r"(a) : "l"(p));
    return a;
}
__device__ __forceinline__ uint64_t make_desc(uint32_t addr) {
    const uint64_t base = (uint64_t(2) << 61) | (uint64_t(1) << 46) |
                          (uint64_t(64) << 32) | (uint64_t(1) << 16);
    return base | ((uint64_t)(addr >> 4) & 0x3FFF);
}

#if HAS_TCGEN05
__device__ __forceinline__ uint32_t elect_one() {
    uint32_t r;
    asm volatile("{\n\t.reg .pred p;\n\telect.sync _|p, 0xFFFFFFFF;\n\tselp.b32 %0, 1, 0, p;\n\t}" : "=r"(r));
    return r;
}
#define TC_MMA_F16_TS(d_tmem, a_tmem, b_desc, idesc, enable_d) do { \
    uint32_t _enable = (enable_d) ? 1 : 0; \
    uint32_t _zero = 0; \
    asm volatile( \
        "{\n\t" \
        ".reg .pred p;\n\t" \
        "setp.ne.u32 p, %6, 0;\n\t" \
        "tcgen05.mma.cta_group::1.kind::f16 [%0], [%1], %2, %3, " \
        "{%4, %4, %4, %4}, p;\n\t" \
        "}" \
        :: "r"(d_tmem), "r"(a_tmem), "l"(b_desc), "r"(idesc), \
           "r"(_zero), "r"(_zero), "r"(_enable) \
        : "memory"); \
} while (0)
#define TC_ALLOC(slot, n)   asm volatile("tcgen05.alloc.cta_group::1.sync.aligned.shared::cta.b32 [%0], %1;" :: "r"(slot), "r"((uint32_t)(n)) : "memory")
#define TC_DEALLOC(t, n)    asm volatile("tcgen05.dealloc.cta_group::1.sync.aligned.b32 %0, %1;" :: "r"(t), "r"((uint32_t)(n)))
#define TC_COMMIT(mb)       asm volatile("tcgen05.commit.cta_group::1.mbarrier::arrive::one.shared::cluster.b64 [%0];" :: "r"(mb) : "memory")
#define TC_WAIT_LD()        asm volatile("tcgen05.wait::ld.sync.aligned;" ::: "memory")
#define TC_WAIT_ST()        asm volatile("tcgen05.wait::st.sync.aligned;" ::: "memory")
#define TC_FENCE_AFTER()    asm volatile("tcgen05.fence::after_thread_sync;" ::: "memory")
#define TC_FENCE_BEFORE()   asm volatile("tcgen05.fence::before_thread_sync;" ::: "memory")
#define MBAR_INIT(mb, c)    asm volatile("mbarrier.init.shared.b64 [%0], %1;" :: "r"(mb), "r"((uint32_t)(c)) : "memory")
#define MBAR_INVAL(mb)      asm volatile("mbarrier.inval.shared.b64 [%0];" :: "r"(mb) : "memory")
#define MBAR_WAIT(mb, ph) do { \
    uint32_t _m = (mb), _p = (ph), _d; \
    asm volatile("{\n\t.reg .pred p;\n\tmbarrier.try_wait.parity.acquire.cta.shared::cta.b64 p, [%1], %2;\n\tselp.b32 %0, 1, 0, p;\n\t}" \
        : "=r"(_d) : "r"(_m), "r"(_p) : "memory"); \
    if (!_d) { \
        asm volatile("{\n\t.reg .pred P1;\n\tWL_%=:\n\tmbarrier.try_wait.parity.acquire.cta.shared::cta.b64 P1, [%0], %1, 0x989680;\n\t@P1 bra.uni WD_%=;\n\tbra.uni WL_%=;\n\tWD_%=:\n\t}" \
            :: "r"(_m), "r"(_p) : "memory"); \
    } \
} while (0)

#define TC_ST_X16(tmem_addr, r) \
    asm volatile( \
        "tcgen05.st.sync.aligned.32x32b.x16.b32 [%0], " \
        "{%1, %2, %3, %4, %5, %6, %7, %8, " \
        " %9, %10, %11, %12, %13, %14, %15, %16};" \
        :: "r"(tmem_addr), \
           "r"((r)[0]),  "r"((r)[1]),  "r"((r)[2]),  "r"((r)[3]), \
           "r"((r)[4]),  "r"((r)[5]),  "r"((r)[6]),  "r"((r)[7]), \
           "r"((r)[8]),  "r"((r)[9]),  "r"((r)[10]), "r"((r)[11]), \
           "r"((r)[12]), "r"((r)[13]), "r"((r)[14]), "r"((r)[15]) \
        : "memory")

#define TC_LD_X32(r, addr) \
    asm volatile( \
        "tcgen05.ld.sync.aligned.32x32b.x32.b32 " \
        "{%0, %1, %2, %3, %4, %5, %6, %7, %8, %9, %10, %11, %12, %13, %14, %15, " \
        " %16, %17, %18, %19, %20, %21, %22, %23, %24, %25, %26, %27, %28, %29, %30, %31}, [%32];" \
        : "=r"((r)[0]), "=r"((r)[1]), "=r"((r)[2]), "=r"((r)[3]), \
          "=r"((r)[4]), "=r"((r)[5]), "=r"((r)[6]), "=r"((r)[7]), \
          "=r"((r)[8]), "=r"((r)[9]), "=r"((r)[10]), "=r"((r)[11]), \
          "=r"((r)[12]), "=r"((r)[13]), "=r"((r)[14]), "=r"((r)[15]), \
          "=r"((r)[16]), "=r"((r)[17]), "=r"((r)[18]), "=r"((r)[19]), \
          "=r"((r)[20]), "=r"((r)[21]), "=r"((r)[22]), "=r"((r)[23]), \
          "=r"((r)[24]), "=r"((r)[25]), "=r"((r)[26]), "=r"((r)[27]), \
          "=r"((r)[28]), "=r"((r)[29]), "=r"((r)[30]), "=r"((r)[31]) \
        : "r"(addr))
#endif  // HAS_TCGEN05

// -------- prep: detect + zero + transpose weights + convert x -> fp16 --------
// block 0: detect; 1..196: zero; 197..452: transpose; 453..6702: x->half
__global__ void prep_kernel(const void* ei, const float* __restrict__ W_rel,
                            const float* __restrict__ W_root,
                            const float* __restrict__ x) {
    int bid = blockIdx.x, tid = threadIdx.x;
    if (bid == 0) {
        __shared__ int bad;
        if (tid == 0) bad = 0;
        __syncthreads();
        long long v = ((const long long*)ei)[tid];
        if (v < 0 || v >= N_NODES) bad = 1;
        __syncthreads();
        if (tid == 0) d_is64 = !bad;
    } else if (bid <= 196) {
        int i = (bid - 1) * 256 + tid;
        if (i < N_NODES) d_deg[i] = 0;
        if (i < NG * HID) d_pooled[i] = 0.0f;
        if (i < NG) d_cnt[i] = 0.0f;
    } else if (bid <= 452) {
        int idx = (bid - 197) * 256 + tid;        // 0..65535
        int m = idx >> 14, e = idx & 16383;
        int n = e >> 7, k = e & 127;
        const float* src = (m & 1) ? (W_root + (m >> 1) * HID * HID)
                                   : (W_rel  + (m >> 1) * HID * HID);
        d_wt[m * HID * HID + n * HID + k] = src[k * HID + n];
    } else {
        // x -> half, 4 elems/thread: (bid-453)*1024 + tid*4
        long long i4 = ((long long)(bid - 453) * 1024 + tid * 4);
        if (i4 < (long long)N_NODES * HID) {
            float4 v = __ldg((const float4*)(x + i4));
            __half2 h0 = __floats2half2_rn(v.x, v.y);
            __half2 h1 = __floats2half2_rn(v.z, v.w);
            *(uint2*)(d_xh + i4) = make_uint2(*(uint32_t*)&h0, *(uint32_t*)&h1);
        }
    }
}

// -------- CSR build (2 edges per thread) --------
__global__ void count_kernel(const void* __restrict__ ei) {
    int e0 = (blockIdx.x * blockDim.x + threadIdx.x) * 2;
    if (e0 < N_EDGES) {
        atomicAdd(&d_deg[load_idx(ei, (long long)N_EDGES + e0)], 1);
        if (e0 + 1 < N_EDGES)
            atomicAdd(&d_deg[load_idx(ei, (long long)N_EDGES + e0 + 1)], 1);
    }
}
__global__ void scan1_kernel() {
    __shared__ int sh[1024];
    int tid = threadIdx.x, i = blockIdx.x * 1024 + tid;
    int v = (i < N_NODES) ? d_deg[i] : 0;
    sh[tid] = v; __syncthreads();
    #pragma unroll
    for (int s = 1; s < 1024; s <<= 1) {
        int t = (tid >= s) ? sh[tid - s] : 0;
        __syncthreads(); sh[tid] += t; __syncthreads();
    }
    if (i < N_NODES) d_rowptr[i] = sh[tid] - v;
    if (tid == 1023) d_bsum[blockIdx.x] = sh[1023];
}
__global__ void scan2_kernel() {
    __shared__ int sh[64];
    int tid = threadIdx.x;
    int v = (tid < SCAN_BLOCKS) ? d_bsum[tid] : 0;
    sh[tid] = v; __syncthreads();
    #pragma unroll
    for (int s = 1; s < 64; s <<= 1) {
        int t = (tid >= s) ? sh[tid - s] : 0;
        __syncthreads(); sh[tid] += t; __syncthreads();
    }
    if (tid < SCAN_BLOCKS) d_btop[tid] = sh[tid] - v;
}
__global__ void scan3_kernel() {
    int i = blockIdx.x * blockDim.x + threadIdx.x;
    if (i < N_NODES) {
        int r = d_rowptr[i] + d_btop[i >> 10];
        d_rowptr[i] = r; d_cursor[i] = r;
    }
    if (i == 0) d_rowptr[N_NODES] = N_EDGES;
}
__global__ void fill_kernel(const void* __restrict__ ei) {
    int e0 = (blockIdx.x * blockDim.x + threadIdx.x) * 2;
    #pragma unroll
    for (int j = 0; j < 2; j++) {
        int e = e0 + j;
        if (e < N_EDGES) {
            int src = load_idx(ei, e);
            int dst = load_idx(ei, (long long)N_EDGES + e);
            d_col[atomicAdd(&d_cursor[dst], 1)] = src;
        }
    }
}

// -------- mean aggregation: warp/node, fp16 gather (half the L2 bytes) --------
__global__ void aggregate_kernel() {
    int gw = (blockIdx.x * blockDim.x + threadIdx.x) >> 5;
    int lane = threadIdx.x & 31;
    if (gw >= N_NODES) return;
    int b = d_rowptr[gw], e = d_rowptr[gw + 1];
    float4 a0 = make_float4(0.f, 0.f, 0.f, 0.f);
    float4 a1 = make_float4(0.f, 0.f, 0.f, 0.f);
    const uint2* x2 = (const uint2*)d_xh;   // 4 halves per uint2; 32/row
    int i = b;
    for (; i + 2 <= e; i += 2) {
        int s0 = __ldg(&d_col[i]);
        int s1 = __ldg(&d_col[i + 1]);
        uint2 u0 = __ldg(&x2[(size_t)s0 * 32 + lane]);
        uint2 u1 = __ldg(&x2[(size_t)s1 * 32 + lane]);
        float2 f00 = __half22float2(*(__half2*)&u0.x);
        float2 f01 = __half22float2(*(__half2*)&u0.y);
        float2 f10 = __half22float2(*(__half2*)&u1.x);
        float2 f11 = __half22float2(*(__half2*)&u1.y);
        a0.x += f00.x; a0.y += f00.y; a0.z += f01.x; a0.w += f01.y;
        a1.x += f10.x; a1.y += f10.y; a1.z += f11.x; a1.w += f11.y;
    }
    if (i < e) {
        int s0 = __ldg(&d_col[i]);
        uint2 u0 = __ldg(&x2[(size_t)s0 * 32 + lane]);
        float2 f00 = __half22float2(*(__half2*)&u0.x);
        float2 f01 = __half22float2(*(__half2*)&u0.y);
        a0.x += f00.x; a0.y += f00.y; a0.z += f01.x; a0.w += f01.y;
    }
    float inv = (e > b) ? 1.0f / (float)(e - b) : 0.0f;
    a0.x = (a0.x + a1.x) * inv; a0.y = (a0.y + a1.y) * inv;
    a0.z = (a0.z + a1.z) * inv; a0.w = (a0.w + a1.w) * inv;
    ((float4*)d_agg)[(size_t)gw * 32 + lane] = a0;
}

#if HAS_TCGEN05
// -------- split f32 -> hi/lo bf16x2 words --------
__device__ __forceinline__ void split4(float4 v, uint32_t* hw, uint32_t* lw) {
    __nv_bfloat16 h0 = __float2bfloat16(v.x), h1 = __float2bfloat16(v.y);
    __nv_bfloat16 h2 = __float2bfloat16(v.z), h3 = __float2bfloat16(v.w);
    __nv_bfloat16 l0 = __float2bfloat16(v.x - __bfloat162float(h0));
    __nv_bfloat16 l1 = __float2bfloat16(v.y - __bfloat162float(h1));
    __nv_bfloat16 l2 = __float2bfloat16(v.z - __bfloat162float(h2));
    __nv_bfloat16 l3 = __float2bfloat16(v.w - __bfloat162float(h3));
    __nv_bfloat162 hp0 = __halves2bfloat162(h0, h1), hp1 = __halves2bfloat162(h2, h3);
    __nv_bfloat162 lp0 = __halves2bfloat162(l0, l1), lp1 = __halves2bfloat162(l2, l3);
    hw[0] = *(uint32_t*)&hp0; hw[1] = *(uint32_t*)&hp1;
    lw[0] = *(uint32_t*)&lp0; lw[1] = *(uint32_t*)&lp1;
}

__device__ __forceinline__ void store_A_tmem(uint32_t tmem, const float* gsrc, int row0) {
    int tid = threadIdx.x;
    if (tid >= 128) return;
    int gr = row0 + tid;
    bool ok = gr < N_NODES;
    const float4* rp = (const float4*)gsrc + (size_t)gr * 32;
    uint32_t woff = ((uint32_t)(tid >> 5)) << 21;
    #pragma unroll
    for (int ch = 0; ch < 4; ch++) {      // 16 TMEM cols (= 32 f32) per chunk
        uint32_t hw[16], lw[16];
        #pragma unroll
        for (int q = 0; q < 8; q++) {
            float4 v = ok ? __ldg(rp + ch * 8 + q) : make_float4(0.f, 0.f, 0.f, 0.f);
            split4(v, hw + q * 2, lw + q * 2);
        }
        TC_ST_X16(tmem + TM_AH + ch * 16 + woff, hw);
        TC_ST_X16(tmem + TM_AL + ch * 16 + woff, lw);
    }
    TC_WAIT_ST();
}

// atom = 8 rows x 64 bf16 (1024B); tiling (16 atom-rows, 2 atom-cols), stride (1,16).
__device__ __forceinline__ void store_W_smem(char* base, const float* wt) {
    int tid = threadIdx.x;
    #pragma unroll
    for (int i = 0; i < 8; i++) {
        int chunk = tid + i * 256;        // 0..2047, each = 8 bf16 (16B)
        int n = chunk >> 4, c8 = chunk & 15;
        const float4* p = (const float4*)(wt + n * HID + c8 * 8);
        float4 v0 = __ldg(p), v1 = __ldg(p + 1);
        uint32_t hw[4], lw[4];
        split4(v0, hw, lw);
        split4(v1, hw + 2, lw + 2);
        int atom_row = n >> 3, inner_row = n & 7;
        int atom_col = c8 >> 3, ic8 = c8 & 7;
        uint32_t b = (uint32_t)((atom_row + atom_col * 16) * 1024 + inner_row * 128 + ic8 * 16);
        b ^= (b >> 3) & 0x70;             // SW128
        *(uint4*)(base + OFF_WH + b) = make_uint4(hw[0], hw[1], hw[2], hw[3]);
        *(uint4*)(base + OFF_WL + b) = make_uint4(lw[0], lw[1], lw[2], lw[3]);
    }
}

// 48 MMAs: 2 N-halves x (Ah,Bh),(Ah,Bl),(Al,Bh) x 8 K-steps (K=16 each).
__device__ __forceinline__ void mma_gemm_ts(uint32_t tmem, uint32_t sbase, bool first) {
    uint64_t bh = make_desc(sbase + OFF_WH);
    uint64_t bl = make_desc(sbase + OFF_WL);
    uint32_t ah = tmem + TM_AH, al = tmem + TM_AL;
    uint32_t apair[3] = {ah, ah, al};
    uint64_t bpair[3] = {bh, bl, bh};
    #pragma unroll
    for (int h = 0; h < 2; h++) {
        #pragma unroll
        for (int p = 0; p < 3; p++) {
            #pragma unroll
            for (int s = 0; s < 8; s++) {
                uint64_t bd = bpair[p] + (uint64_t)(h * 512 + (s >> 2) * 1024 + (s & 3) * 2);
                TC_MMA_F16_TS(tmem + TM_D + h * 64, apair[p] + s * 8, bd, BF16_IDESC_N64,
                              !(first && p == 0 && s == 0));
            }
        }
    }
}
#endif

// -------- layer: out = relu(LN(agg@Wrel + brel + x@Wroot)) --------
// Weights from d_wt device symbol selected by `layer` inside device code
// (host-side &d_wt is the HOST shadow; GB300 ATS reads zeros — rounds-4..9 bug).
__global__ void __launch_bounds__(256, 2) __cluster_dims__(1, 1, 1) layer_tc(
    const float* __restrict__ xin,        // nullptr -> d_bufA
    const float* __restrict__ brel,
    const float* __restrict__ gam,
    const float* __restrict__ bet,
    int layer, int outsel)
{
    extern __shared__ char smem_raw[];
    const float* xp = xin ? xin : d_bufA;
    float* outp = outsel ? d_bufB : d_bufA;
    const float* wtrel  = d_wt + (2 * layer)     * HID * HID;
    const float* wtroot = d_wt + (2 * layer + 1) * HID * HID;
    int tid = threadIdx.x;
    int row0 = blockIdx.x * 128;

#if HAS_TCGEN05
    uint32_t sraw = smem_u32(smem_raw);
    uint32_t sbase = (sraw + 1023u) & ~1023u;   // SW128 tiles need 1024B alignment
    char* base = smem_raw + (sbase - sraw);
    int wid = tid >> 5;

    float* sBias = (float*)(base + OFF_BIAS);
    float* sGam  = (float*)(base + OFF_GAM);
    float* sBet  = (float*)(base + OFF_BET);
    if (tid < 128) { sBias[tid] = brel[tid]; sGam[tid] = gam[tid]; sBet[tid] = bet[tid]; }

    // alloc by warp 0 ONLY; no relinquish (hi-wid-first arbiter trap).
    if (wid == 0) { TC_ALLOC(sbase + OFF_TMEM, TMEM_COLS); }
    if (tid == 0) { MBAR_INIT(sbase + OFF_MBAR0, 1); MBAR_INIT(sbase + OFF_MBAR1, 1); }
    __syncthreads();
    uint32_t tmem;
    asm volatile("ld.shared.b32 %0, [%1];" : "=r"(tmem) : "r"(sbase + OFF_TMEM));

    // ---- GEMM 1: D = agg @ Wrel^T ----
    store_A_tmem(tmem, d_agg, row0);
    store_W_smem(base, wtrel);
    TC_FENCE_BEFORE();
    __syncthreads();
    if (wid == 0) {
        TC_FENCE_AFTER();
        if (elect_one()) {
            mma_gemm_ts(tmem, sbase, true);
            TC_COMMIT(sbase + OFF_MBAR0);
        }
    }
    MBAR_WAIT(sbase + OFF_MBAR0, 0);

    // ---- GEMM 2: D += x @ Wroot^T ----
    store_A_tmem(tmem, xp, row0);
    store_W_smem(base, wtroot);
    TC_FENCE_BEFORE();
    __syncthreads();
    if (wid == 0) {
        TC_FENCE_AFTER();
        if (elect_one()) {
            mma_gemm_ts(tmem, sbase, false);
            TC_COMMIT(sbase + OFF_MBAR1);
        }
    }
    MBAR_WAIT(sbase + OFF_MBAR1, 0);
    TC_FENCE_AFTER();

    // ---- epilogue (register-lean, 2-pass): thread = row ----
    float* stg = (float*)(base + OFF_WH);   // stride 132 floats (33 float4)
    if (tid < 128) {
        float sum = 0.0f, sq = 0.0f;
        #pragma unroll
        for (int ch = 0; ch < 4; ch++) {
            uint32_t t[32];
            TC_LD_X32(t, tmem + TM_D + ch * 32);
            TC_WAIT_LD();
            #pragma unroll
            for (int c = 0; c < 32; c++) {
                float v = __uint_as_float(t[c]) + sBias[ch * 32 + c];
                sum += v;
                sq += v * v;
            }
        }
        float mu = sum * (1.0f / 128.0f);
        float var = sq * (1.0f / 128.0f) - mu * mu;
        float rs = rsqrtf(fmaxf(var, 0.0f) + EPS);
        int r = tid;
        #pragma unroll
        for (int ch = 0; ch < 4; ch++) {
            uint32_t t[32];
            TC_LD_X32(t, tmem + TM_D + ch * 32);
            TC_WAIT_LD();
            #pragma unroll
            for (int c4 = 0; c4 < 8; c4++) {
                float4 ov;
                float* o = (float*)&ov;
                #pragma unroll
                for (int j = 0; j < 4; j++) {
                    int cc = c4 * 4 + j;
                    int c = ch * 32 + cc;
                    float v = __uint_as_float(t[cc]) + sBias[c];
                    o[j] = fmaxf(sGam[c] * (v - mu) * rs + sBet[c], 0.0f);
                }
                ((float4*)stg)[r * 33 + ch * 8 + c4] = ov;
            }
        }
        TC_FENCE_BEFORE();
    }
    __syncthreads();

    // coalesced copy staging -> global (+ fp16 copy for next layer's gather)
    #pragma unroll
    for (int i = 0; i < 16; i++) {
        int idx = tid + i * 256;
        int r = idx >> 5, c4 = idx & 31;
        int gr = row0 + r;
        if (gr < N_NODES) {
            float4 v = ((float4*)stg)[r * 33 + c4];
            ((float4*)outp)[(size_t)gr * 32 + c4] = v;
            if (!outsel) {
                __half2 h0 = __floats2half2_rn(v.x, v.y);
                __half2 h1 = __floats2half2_rn(v.z, v.w);
                ((uint2*)d_xh)[(size_t)gr * 32 + c4] =
                    make_uint2(*(uint32_t*)&h0, *(uint32_t*)&h1);
            }
        }
    }
    __syncthreads();

    if (tid == 0) { MBAR_INVAL(sbase + OFF_MBAR0); MBAR_INVAL(sbase + OFF_MBAR1); }
    __syncthreads();
    if (wid == 0) { TC_DEALLOC(tmem, TMEM_COLS); }

#else
    // ---- SIMT fallback (generic sm_103 pass only) ----
    char* smem = smem_raw;
    float (*As)[132] = (float(*)[132])(smem);
    float (*Bs)[128] = (float(*)[128])(smem + 32 * 132 * 4);
    int lane = tid & 31;
    int w = tid >> 5;
    int w16 = w * 16;

    float acc[16][4];
    #pragma unroll
    for (int r = 0; r < 16; r++)
        #pragma unroll
        for (int j = 0; j < 4; j++) acc[r][j] = 0.0f;

    #pragma unroll
    for (int pass = 0; pass < 2; pass++) {
        const float* A = pass ? xp : d_agg;
        const float* Wt = pass ? wtroot : wtrel;
        #pragma unroll
        for (int k0 = 0; k0 < 128; k0 += 32) {
            __syncthreads();
            #pragma unroll
            for (int i = 0; i < 16; i++) {
                int r = w + i * 8;
                int gr = row0 + r;
                As[lane][r] = (gr < N_NODES) ? A[(size_t)gr * HID + k0 + lane] : 0.0f;
            }
            #pragma unroll
            for (int i = 0; i < 16; i++) {
                int idx = tid + i * 256;
                int kk = idx >> 7, nn = idx & 127;
                Bs[kk][nn] = Wt[(size_t)nn * HID + k0 + kk];
            }
            __syncthreads();
            #pragma unroll
            for (int kc = 0; kc < 32; kc++) {
                float4 b4 = *(const float4*)&Bs[kc][lane * 4];
                float ar[16];
                *(float4*)&ar[0]  = *(const float4*)&As[kc][w16];
                *(float4*)&ar[4]  = *(const float4*)&As[kc][w16 + 4];
                *(float4*)&ar[8]  = *(const float4*)&As[kc][w16 + 8];
                *(float4*)&ar[12] = *(const float4*)&As[kc][w16 + 12];
                #pragma unroll
                for (int r = 0; r < 16; r++) {
                    acc[r][0] += ar[r] * b4.x;
                    acc[r][1] += ar[r] * b4.y;
                    acc[r][2] += ar[r] * b4.z;
                    acc[r][3] += ar[r] * b4.w;
                }
            }
        }
    }

    int c0 = lane * 4;
    float4 bb = *(const float4*)&brel[c0];
    float4 gg = *(const float4*)&gam[c0];
    float4 be = *(const float4*)&bet[c0];
    #pragma unroll
    for (int r = 0; r < 16; r++) {
        int gr = row0 + w16 + r;
        if (gr >= N_NODES) break;
        float v0 = acc[r][0] + bb.x, v1 = acc[r][1] + bb.y;
        float v2 = acc[r][2] + bb.z, v3 = acc[r][3] + bb.w;
        float mu = warp_sum(v0 + v1 + v2 + v3) * (1.0f / 128.0f);
        float d0 = v0 - mu, d1 = v1 - mu, d2 = v2 - mu, d3 = v3 - mu;
        float var = warp_sum(d0 * d0 + d1 * d1 + d2 * d2 + d3 * d3) * (1.0f / 128.0f);
        float rs = rsqrtf(var + EPS);
        float4 ov;
        ov.x = fmaxf(gg.x * d0 * rs + be.x, 0.0f);
        ov.y = fmaxf(gg.y * d1 * rs + be.y, 0.0f);
        ov.z = fmaxf(gg.z * d2 * rs + be.z, 0.0f);
        ov.w = fmaxf(gg.w * d3 * rs + be.w, 0.0f);
        *(float4*)&outp[(size_t)gr * HID + c0] = ov;
        if (!outsel) {
            __half2 h0 = __floats2half2_rn(ov.x, ov.y);
            __half2 h1 = __floats2half2_rn(ov.z, ov.w);
            ((uint2*)d_xh)[(size_t)gr * 32 + lane] =
                make_uint2(*(uint32_t*)&h0, *(uint32_t*)&h1);
        }
    }
#endif
}

// -------- graph mean pooling: warp handles 32 consecutive rows, run-length --------
__global__ void pool_kernel(const void* __restrict__ batch) {
    int warp = (blockIdx.x * blockDim.x + threadIdx.x) >> 5;
    int lane = threadIdx.x & 31;
    int r0 = warp * 32;
    if (r0 >= N_NODES) return;
    int rend = r0 + 32; if (rend > N_NODES) rend = N_NODES;
    int curg = -1, cnt = 0;
    float p0 = 0.f, p1 = 0.f, p2 = 0.f, p3 = 0.f;
    for (int r = r0; r < rend; r++) {
        int g = load_idx(batch, r);
        float4 v = ((const float4*)d_bufB)[(size_t)r * 32 + lane];
        if (g != curg) {
            if (curg >= 0) {
                float* pp = &d_pooled[curg * HID + lane * 4];
                atomicAdd(pp + 0, p0); atomicAdd(pp + 1, p1);
                atomicAdd(pp + 2, p2); atomicAdd(pp + 3, p3);
                if (lane == 0) atomicAdd(&d_cnt[curg], (float)cnt);
            }
            curg = g; cnt = 1; p0 = v.x; p1 = v.y; p2 = v.z; p3 = v.w;
        } else { p0 += v.x; p1 += v.y; p2 += v.z; p3 += v.w; cnt++; }
    }
    if (curg >= 0) {
        float* pp = &d_pooled[curg * HID + lane * 4];
        atomicAdd(pp + 0, p0); atomicAdd(pp + 1, p1);
        atomicAdd(pp + 2, p2); atomicAdd(pp + 3, p3);
        if (lane == 0) atomicAdd(&d_cnt[curg], (float)cnt);
    }
}

__global__ void cls_kernel(const float* __restrict__ Wc, const float* __restrict__ bc,
                           float* __restrict__ out) {
    int g = blockIdx.x;
    int o = threadIdx.x >> 5, lane = threadIdx.x & 31;
    if (o >= OUTD) return;
    float inv = 1.0f / fmaxf(d_cnt[g], 1.0f);
    float s = 0.0f;
    for (int k = lane; k < HID; k += 32)
        s += d_pooled[g * HID + k] * Wc[k * OUTD + o];
    s = warp_sum(s);
    if (lane == 0) out[g * OUTD + o] = s * inv + bc[o];
}

extern "C" void kernel_launch(void* const* d_in, const int* in_sizes, int n_in,
                              void* d_out, int out_size) {
    const float* x      = (const float*)d_in[0];
    const void*  ei     = d_in[1];
    const void*  batch  = d_in[2];
    const float* W_rel  = (const float*)d_in[3];
    const float* b_rel  = (const float*)d_in[4];
    const float* W_root = (const float*)d_in[5];
    const float* gamma  = (const float*)d_in[6];
    const float* beta   = (const float*)d_in[7];
    const float* Wc     = (const float*)d_in[8];
    const float* bc     = (const float*)d_in[9];
    float* out = (float*)d_out;

    cudaFuncSetAttribute(layer_tc, cudaFuncAttributeMaxDynamicSharedMemorySize, SMEM_TOTAL);

    prep_kernel<<<453 + 6250, 256>>>(ei, W_rel, W_root, x);
    count_kernel<<<(N_EDGES / 2 + 255) / 256, 256>>>(ei);
    scan1_kernel<<<SCAN_BLOCKS, 1024>>>();
    scan2_kernel<<<1, 64>>>();
    scan3_kernel<<<SCAN_BLOCKS, 1024>>>();
    fill_kernel<<<(N_EDGES / 2 + 255) / 256, 256>>>(ei);

    int ntiles = (N_NODES + 127) / 128;
    // layer 0: gathers d_xh (fp16 x), GEMM uses f32 x -> bufA (+ fp16 copy to d_xh)
    aggregate_kernel<<<N_NODES / 8, 256>>>();
    layer_tc<<<ntiles, 256, SMEM_TOTAL>>>(x, b_rel, gamma, beta, 0, 0);
    // layer 1: gathers d_xh (fp16 bufA), GEMM uses f32 bufA -> bufB
    aggregate_kernel<<<N_NODES / 8, 256>>>();
    layer_tc<<<ntiles, 256, SMEM_TOTAL>>>(nullptr, b_rel + HID, gamma + HID, beta + HID, 1, 1);

    pool_kernel<<<196, 256>>>(batch);
    cls_kernel<<<NG, 320>>>(Wc, bc, out);
}

// round 13
// speedup vs baseline: 1.4346x; 1.4346x over previous
#include <cuda_runtime.h>
#include <cuda_bf16.h>
#include <cuda_fp16.h>
#include <cstdint>

#define N_NODES 50000
#define N_EDGES 800000
#define HID 128
#define NG 128
#define OUTD 10
#define EPS 1e-5f
#define SCAN_BLOCKS 49

#if defined(__CUDA_ARCH_FEAT_SM103_ALL) || defined(__CUDA_ARCH_FEAT_SM100_ALL) || \
    (defined(__CUDA_ARCH_SPECIFIC__))
#define HAS_TCGEN05 1
#else
#define HAS_TCGEN05 0
#endif

// ---- layer_tc smem layout (byte offsets from 1024-aligned base) ----
#define OFF_TMEM 0
#define OFF_MBAR0 8
#define OFF_BIAS 64
#define OFF_GAM  576
#define OFF_BET  1088
#define OFF_WREL 2048                   // Wrel fp16 blocked-atom tile, 32KB
#define OFF_WROOT (OFF_WREL + 32768)    // Wroot fp16 tile, 32KB
#define SMEM_USED (OFF_WROOT + 32768)   // 67584; staging (128*272B) overlays WREL
#define SMEM_TOTAL (SMEM_USED + 1024)   // + alignment slack (~67KB; x2 CTAs fits)
// kind::f16 idesc, fp16 inputs (atype=btype=0), N=64, M=128:
// dtypeF32(1<<4) | (64/8)<<17 | (128/16)<<24 = 0x8100010
#define FP16_IDESC_N64 0x8100010u
#define TMEM_COLS 256                   // D[0,128) + A_agg[128,192) + A_x[192,256)
#define TM_D  0
#define TM_AG 128
#define TM_AX 192

// -------- device scratch --------
__device__ int    d_is64;
__device__ int    d_deg[N_NODES];
__device__ int    d_rowptr[N_NODES + 1];
__device__ int    d_cursor[N_NODES];
__device__ int    d_bsum[SCAN_BLOCKS];
__device__ int    d_col[N_EDGES];
__device__ __align__(16) float  d_wt[4 * HID * HID];    // f32 [N][K] (SIMT fallback only)
__device__ __align__(16) __half d_wtc[4 * HID * HID];   // fp16 blocked-atom swizzled image
__device__ __align__(16) __half d_xh[N_NODES * HID];    // fp16 features (in/out of layer0)
__device__ __align__(16) __half d_yh[N_NODES * HID];    // fp16 layer1 output
__device__ __align__(16) __half d_aggh[N_NODES * HID];  // fp16 aggregation
__device__ __align__(16) float  d_pooled[NG * HID];
__device__ float  d_cnt[NG];

__device__ __forceinline__ float warp_sum(float v) {
    #pragma unroll
    for (int o = 16; o > 0; o >>= 1) v += __shfl_xor_sync(0xFFFFFFFFu, v, o);
    return v;
}
__device__ __forceinline__ int load_idx(const void* p, long long i) {
    if (d_is64) return (int)((const long long*)p)[i];
    return ((const int*)p)[i];
}
__device__ __forceinline__ uint32_t smem_u32(const void* p) {
    uint32_t a;
    asm("{ .reg .u64 t; cvta.to.shared.u64 t, %1; cvt.u32.u64 %0, t; }" : "=r"(a) : "l"(p));
    return a;
}
__device__ __forceinline__ uint64_t make_desc(uint32_t addr) {
    const uint64_t base = (uint64_t(2) << 61) | (uint64_t(1) << 46) |
                          (uint64_t(64) << 32) | (uint64_t(1) << 16);
    return base | ((uint64_t)(addr >> 4) & 0x3FFF);
}
// blocked-atom + SW128 byte offset for element group (n, k8) of a [N=128][K=128] 2B tile
__device__ __forceinline__ uint32_t watom_off(int n, int k8) {
    uint32_t b = (uint32_t)(((n >> 3) + (k8 >> 3) * 16) * 1024 + (n & 7) * 128 + (k8 & 7) * 16);
    return b ^ ((b >> 3) & 0x70);
}

#if HAS_TCGEN05
__device__ __forceinline__ uint32_t elect_one() {
    uint32_t r;
    asm volatile("{\n\t.reg .pred p;\n\telect.sync _|p, 0xFFFFFFFF;\n\tselp.b32 %0, 1, 0, p;\n\t}" : "=r"(r));
    return r;
}
#define TC_MMA_F16_TS(d_tmem, a_tmem, b_desc, idesc, enable_d) do { \
    uint32_t _enable = (enable_d) ? 1 : 0; \
    uint32_t _zero = 0; \
    asm volatile( \
        "{\n\t" \
        ".reg .pred p;\n\t" \
        "setp.ne.u32 p, %6, 0;\n\t" \
        "tcgen05.mma.cta_group::1.kind::f16 [%0], [%1], %2, %3, " \
        "{%4, %4, %4, %4}, p;\n\t" \
        "}" \
        :: "r"(d_tmem), "r"(a_tmem), "l"(b_desc), "r"(idesc), \
           "r"(_zero), "r"(_zero), "r"(_enable) \
        : "memory"); \
} while (0)
#define TC_ALLOC(slot, n)   asm volatile("tcgen05.alloc.cta_group::1.sync.aligned.shared::cta.b32 [%0], %1;" :: "r"(slot), "r"((uint32_t)(n)) : "memory")
#define TC_DEALLOC(t, n)    asm volatile("tcgen05.dealloc.cta_group::1.sync.aligned.b32 %0, %1;" :: "r"(t), "r"((uint32_t)(n)))
#define TC_COMMIT(mb)       asm volatile("tcgen05.commit.cta_group::1.mbarrier::arrive::one.shared::cluster.b64 [%0];" :: "r"(mb) : "memory")
#define TC_WAIT_LD()        asm volatile("tcgen05.wait::ld.sync.aligned;" ::: "memory")
#define TC_WAIT_ST()        asm volatile("tcgen05.wait::st.sync.aligned;" ::: "memory")
#define TC_FENCE_AFTER()    asm volatile("tcgen05.fence::after_thread_sync;" ::: "memory")
#define TC_FENCE_BEFORE()   asm volatile("tcgen05.fence::before_thread_sync;" ::: "memory")
#define MBAR_INIT(mb, c)    asm volatile("mbarrier.init.shared.b64 [%0], %1;" :: "r"(mb), "r"((uint32_t)(c)) : "memory")
#define MBAR_INVAL(mb)      asm volatile("mbarrier.inval.shared.b64 [%0];" :: "r"(mb) : "memory")
#define MBAR_WAIT(mb, ph) do { \
    uint32_t _m = (mb), _p = (ph), _d; \
    asm volatile("{\n\t.reg .pred p;\n\tmbarrier.try_wait.parity.acquire.cta.shared::cta.b64 p, [%1], %2;\n\tselp.b32 %0, 1, 0, p;\n\t}" \
        : "=r"(_d) : "r"(_m), "r"(_p) : "memory"); \
    if (!_d) { \
        asm volatile("{\n\t.reg .pred P1;\n\tWL_%=:\n\tmbarrier.try_wait.parity.acquire.cta.shared::cta.b64 P1, [%0], %1, 0x989680;\n\t@P1 bra.uni WD_%=;\n\tbra.uni WL_%=;\n\tWD_%=:\n\t}" \
            :: "r"(_m), "r"(_p) : "memory"); \
    } \
} while (0)

#define TC_ST_X16(tmem_addr, r) \
    asm volatile( \
        "tcgen05.st.sync.aligned.32x32b.x16.b32 [%0], " \
        "{%1, %2, %3, %4, %5, %6, %7, %8, " \
        " %9, %10, %11, %12, %13, %14, %15, %16};" \
        :: "r"(tmem_addr), \
           "r"((r)[0]),  "r"((r)[1]),  "r"((r)[2]),  "r"((r)[3]), \
           "r"((r)[4]),  "r"((r)[5]),  "r"((r)[6]),  "r"((r)[7]), \
           "r"((r)[8]),  "r"((r)[9]),  "r"((r)[10]), "r"((r)[11]), \
           "r"((r)[12]), "r"((r)[13]), "r"((r)[14]), "r"((r)[15]) \
        : "memory")

#define TC_LD_X32(r, addr) \
    asm volatile( \
        "tcgen05.ld.sync.aligned.32x32b.x32.b32 " \
        "{%0, %1, %2, %3, %4, %5, %6, %7, %8, %9, %10, %11, %12, %13, %14, %15, " \
        " %16, %17, %18, %19, %20, %21, %22, %23, %24, %25, %26, %27, %28, %29, %30, %31}, [%32];" \
        : "=r"((r)[0]), "=r"((r)[1]), "=r"((r)[2]), "=r"((r)[3]), \
          "=r"((r)[4]), "=r"((r)[5]), "=r"((r)[6]), "=r"((r)[7]), \
          "=r"((r)[8]), "=r"((r)[9]), "=r"((r)[10]), "=r"((r)[11]), \
          "=r"((r)[12]), "=r"((r)[13]), "=r"((r)[14]), "=r"((r)[15]), \
          "=r"((r)[16]), "=r"((r)[17]), "=r"((r)[18]), "=r"((r)[19]), \
          "=r"((r)[20]), "=r"((r)[21]), "=r"((r)[22]), "=r"((r)[23]), \
          "=r"((r)[24]), "=r"((r)[25]), "=r"((r)[26]), "=r"((r)[27]), \
          "=r"((r)[28]), "=r"((r)[29]), "=r"((r)[30]), "=r"((r)[31]) \
        : "r"(addr))
#endif  // HAS_TCGEN05

// -------- prep: detect + zero + weight prep (f32 + fp16-image) + x -> fp16 --------
// bid 0: detect; 1..196: zero; 197..452: f32 transpose; 453..484: fp16 blocked image;
// 485..6734: x -> fp16
__global__ void prep_kernel(const void* ei, const float* __restrict__ W_rel,
                            const float* __restrict__ W_root,
                            const float* __restrict__ x) {
    int bid = blockIdx.x, tid = threadIdx.x;
    if (bid == 0) {
        __shared__ int bad;
        if (tid == 0) bad = 0;
        __syncthreads();
        long long v = ((const long long*)ei)[tid];
        if (v < 0 || v >= N_NODES) bad = 1;
        __syncthreads();
        if (tid == 0) d_is64 = !bad;
    } else if (bid <= 196) {
        int i = (bid - 1) * 256 + tid;
        if (i < N_NODES) d_deg[i] = 0;
        if (i < NG * HID) d_pooled[i] = 0.0f;
        if (i < NG) d_cnt[i] = 0.0f;
    } else if (bid <= 452) {
        int idx = (bid - 197) * 256 + tid;        // 0..65535 (f32 transpose for fallback)
        int m = idx >> 14, e = idx & 16383;
        int n = e >> 7, k = e & 127;
        const float* src = (m & 1) ? (W_root + (m >> 1) * HID * HID)
                                   : (W_rel  + (m >> 1) * HID * HID);
        d_wt[m * HID * HID + n * HID + k] = src[k * HID + n];
    } else if (bid <= 484) {
        // fp16 blocked-atom swizzled weight image: item = (m, n, k8)
        int item = (bid - 453) * 256 + tid;       // 0..8191
        int m = item >> 11, rem = item & 2047;
        int n = rem >> 4, k8 = rem & 15;
        const float* src = (m & 1) ? (W_root + (m >> 1) * HID * HID)
                                   : (W_rel  + (m >> 1) * HID * HID);
        uint32_t w[4];
        #pragma unroll
        for (int t = 0; t < 4; t++) {
            float f0 = src[(k8 * 8 + t * 2)     * HID + n];
            float f1 = src[(k8 * 8 + t * 2 + 1) * HID + n];
            __half2 h = __floats2half2_rn(f0, f1);
            w[t] = *(uint32_t*)&h;
        }
        *(uint4*)((char*)d_wtc + m * 32768 + watom_off(n, k8)) =
            make_uint4(w[0], w[1], w[2], w[3]);
    } else {
        long long i4 = ((long long)(bid - 485) * 1024 + tid * 4);
        if (i4 < (long long)N_NODES * HID) {
            float4 v = __ldg((const float4*)(x + i4));
            __half2 h0 = __floats2half2_rn(v.x, v.y);
            __half2 h1 = __floats2half2_rn(v.z, v.w);
            *(uint2*)(d_xh + i4) = make_uint2(*(uint32_t*)&h0, *(uint32_t*)&h1);
        }
    }
}

// -------- CSR build --------
__global__ void count_kernel(const void* __restrict__ ei) {
    int e0 = (blockIdx.x * blockDim.x + threadIdx.x) * 2;
    if (e0 < N_EDGES) {
        atomicAdd(&d_deg[load_idx(ei, (long long)N_EDGES + e0)], 1);
        if (e0 + 1 < N_EDGES)
            atomicAdd(&d_deg[load_idx(ei, (long long)N_EDGES + e0 + 1)], 1);
    }
}
__global__ void scanA_kernel() {
    __shared__ int sh[1024];
    int tid = threadIdx.x, i = blockIdx.x * 1024 + tid;
    int v = (i < N_NODES) ? d_deg[i] : 0;
    sh[tid] = v; __syncthreads();
    #pragma unroll
    for (int s = 1; s < 1024; s <<= 1) {
        int t = (tid >= s) ? sh[tid - s] : 0;
        __syncthreads(); sh[tid] += t; __syncthreads();
    }
    if (i < N_NODES) d_rowptr[i] = sh[tid] - v;   // block-local exclusive
    if (tid == 1023) d_bsum[blockIdx.x] = sh[1023];
}
__global__ void scanB_kernel() {
    __shared__ int pre;
    int b = blockIdx.x, tid = threadIdx.x;
    if (tid == 0) {
        int s = 0;
        for (int j = 0; j < b; j++) s += d_bsum[j];
        pre = s;
    }
    __syncthreads();
    int i = b * 1024 + tid;
    if (i < N_NODES) {
        int r = d_rowptr[i] + pre;
        d_rowptr[i] = r; d_cursor[i] = r;
    }
    if (i == 0) d_rowptr[N_NODES] = N_EDGES;
}
__global__ void fill_kernel(const void* __restrict__ ei) {
    int e0 = (blockIdx.x * blockDim.x + threadIdx.x) * 2;
    #pragma unroll
    for (int j = 0; j < 2; j++) {
        int e = e0 + j;
        if (e < N_EDGES) {
            int src = load_idx(ei, e);
            int dst = load_idx(ei, (long long)N_EDGES + e);
            d_col[atomicAdd(&d_cursor[dst], 1)] = src;
        }
    }
}

// -------- mean aggregation: fp16 gather from d_xh -> fp16 d_aggh --------
__global__ void aggregate_kernel() {
    int gw = (blockIdx.x * blockDim.x + threadIdx.x) >> 5;
    int lane = threadIdx.x & 31;
    if (gw >= N_NODES) return;
    int b = d_rowptr[gw], e = d_rowptr[gw + 1];
    float4 a0 = make_float4(0.f, 0.f, 0.f, 0.f);
    float4 a1 = make_float4(0.f, 0.f, 0.f, 0.f);
    const uint2* x2 = (const uint2*)d_xh;   // 4 halves per uint2; 32 per row
    int i = b;
    for (; i + 2 <= e; i += 2) {
        int s0 = __ldg(&d_col[i]);
        int s1 = __ldg(&d_col[i + 1]);
        uint2 u0 = __ldg(&x2[(size_t)s0 * 32 + lane]);
        uint2 u1 = __ldg(&x2[(size_t)s1 * 32 + lane]);
        float2 f00 = __half22float2(*(__half2*)&u0.x);
        float2 f01 = __half22float2(*(__half2*)&u0.y);
        float2 f10 = __half22float2(*(__half2*)&u1.x);
        float2 f11 = __half22float2(*(__half2*)&u1.y);
        a0.x += f00.x; a0.y += f00.y; a0.z += f01.x; a0.w += f01.y;
        a1.x += f10.x; a1.y += f10.y; a1.z += f11.x; a1.w += f11.y;
    }
    if (i < e) {
        int s0 = __ldg(&d_col[i]);
        uint2 u0 = __ldg(&x2[(size_t)s0 * 32 + lane]);
        float2 f00 = __half22float2(*(__half2*)&u0.x);
        float2 f01 = __half22float2(*(__half2*)&u0.y);
        a0.x += f00.x; a0.y += f00.y; a0.z += f01.x; a0.w += f01.y;
    }
    float inv = (e > b) ? 1.0f / (float)(e - b) : 0.0f;
    __half2 h0 = __floats2half2_rn((a0.x + a1.x) * inv, (a0.y + a1.y) * inv);
    __half2 h1 = __floats2half2_rn((a0.z + a1.z) * inv, (a0.w + a1.w) * inv);
    ((uint2*)d_aggh)[(size_t)gw * 32 + lane] = make_uint2(*(uint32_t*)&h0, *(uint32_t*)&h1);
}

#if HAS_TCGEN05
// -------- store fp16 A row (128 halves) to 64 TMEM cols, thread = row --------
__device__ __forceinline__ void store_A_tmem_h(uint32_t tcol, const __half* src, int row0) {
    int tid = threadIdx.x;
    if (tid >= 128) return;
    int gr = row0 + tid;
    bool ok = gr < N_NODES;
    const uint4* rp = (const uint4*)(src + (size_t)gr * HID);
    uint32_t woff = ((uint32_t)(tid >> 5)) << 21;
    #pragma unroll
    for (int ch = 0; ch < 4; ch++) {      // 16 cols (= 32 halves) per chunk
        uint32_t r[16];
        #pragma unroll
        for (int q = 0; q < 4; q++) {
            uint4 v = ok ? __ldg(rp + ch * 4 + q) : make_uint4(0, 0, 0, 0);
            r[q * 4 + 0] = v.x; r[q * 4 + 1] = v.y;
            r[q * 4 + 2] = v.z; r[q * 4 + 3] = v.w;
        }
        TC_ST_X16(tcol + ch * 16 + woff, r);
    }
}

// 32 MMAs, single phase: GEMM g in {agg@Wrel, x@Wroot}, N-half h, K-step s.
__device__ __forceinline__ void mma_both(uint32_t tmem, uint32_t sbase) {
    uint64_t wdesc[2] = {make_desc(sbase + OFF_WREL), make_desc(sbase + OFF_WROOT)};
    uint32_t atile[2] = {tmem + TM_AG, tmem + TM_AX};
    #pragma unroll
    for (int g = 0; g < 2; g++) {
        #pragma unroll
        for (int h = 0; h < 2; h++) {
            #pragma unroll
            for (int s = 0; s < 8; s++) {
                uint64_t bd = wdesc[g] + (uint64_t)(h * 512 + (s >> 2) * 1024 + (s & 3) * 2);
                TC_MMA_F16_TS(tmem + TM_D + h * 64, atile[g] + s * 8, bd, FP16_IDESC_N64,
                              !(g == 0 && s == 0));
            }
        }
    }
}
#endif

// -------- layer: out_h = fp16(relu(LN(agg@Wrel + brel + x@Wroot))) --------
// Weights/buffers via device symbols selected inside device code (host-side
// symbol addresses are HOST shadows; GB300 ATS reads zeros — rounds-4..9 bug).
__global__ void __launch_bounds__(256, 2) __cluster_dims__(1, 1, 1) layer_tc(
    const float* __restrict__ brel,
    const float* __restrict__ gam,
    const float* __restrict__ bet,
    int layer, int outsel)
{
    extern __shared__ char smem_raw[];
    __half* outh = outsel ? d_yh : d_xh;
    const __half* wrel  = d_wtc + (2 * layer)     * HID * HID;
    const __half* wroot = d_wtc + (2 * layer + 1) * HID * HID;
    int tid = threadIdx.x;
    int row0 = blockIdx.x * 128;

#if HAS_TCGEN05
    uint32_t sraw = smem_u32(smem_raw);
    uint32_t sbase = (sraw + 1023u) & ~1023u;   // SW128 tiles need 1024B alignment
    char* base = smem_raw + (sbase - sraw);
    int wid = tid >> 5;

    float* sBias = (float*)(base + OFF_BIAS);
    float* sGam  = (float*)(base + OFF_GAM);
    float* sBet  = (float*)(base + OFF_BET);
    if (tid < 128) { sBias[tid] = brel[tid]; sGam[tid] = gam[tid]; sBet[tid] = bet[tid]; }

    // alloc by warp 0 ONLY; no relinquish (hi-wid-first arbiter trap).
    if (wid == 0) { TC_ALLOC(sbase + OFF_TMEM, TMEM_COLS); }
    if (tid == 0) { MBAR_INIT(sbase + OFF_MBAR0, 1); }
    __syncthreads();
    uint32_t tmem;
    asm volatile("ld.shared.b32 %0, [%1];" : "=r"(tmem) : "r"(sbase + OFF_TMEM));

    // ---- single phase: A_agg + A_x -> TMEM, Wrel + Wroot -> smem (linear copy) ----
    store_A_tmem_h(tmem + TM_AG, d_aggh, row0);
    store_A_tmem_h(tmem + TM_AX, d_xh,   row0);
    if (tid < 128) TC_WAIT_ST();
    {
        const uint4* wr = (const uint4*)wrel;
        const uint4* wo = (const uint4*)wroot;
        uint4* sr = (uint4*)(base + OFF_WREL);
        uint4* so = (uint4*)(base + OFF_WROOT);
        #pragma unroll
        for (int i = 0; i < 8; i++) {
            int idx = tid + i * 256;      // 0..2047
            sr[idx] = __ldg(wr + idx);
            so[idx] = __ldg(wo + idx);
        }
    }
    TC_FENCE_BEFORE();
    __syncthreads();
    if (wid == 0) {
        TC_FENCE_AFTER();
        if (elect_one()) {
            mma_both(tmem, sbase);
            TC_COMMIT(sbase + OFF_MBAR0);
        }
    }
    MBAR_WAIT(sbase + OFF_MBAR0, 0);
    TC_FENCE_AFTER();

    // ---- epilogue (register-lean, 2-pass): thread = row; stage fp16 ----
    char* stg = base + OFF_WREL;          // 128 rows x 272B (17 uint4) stride
    if (tid < 128) {
        float sum = 0.0f, sq = 0.0f;
        #pragma unroll
        for (int ch = 0; ch < 4; ch++) {
            uint32_t t[32];
            TC_LD_X32(t, tmem + TM_D + ch * 32);
            TC_WAIT_LD();
            #pragma unroll
            for (int c = 0; c < 32; c++) {
                float v = __uint_as_float(t[c]) + sBias[ch * 32 + c];
                sum += v;
                sq += v * v;
            }
        }
        float mu = sum * (1.0f / 128.0f);
        float var = sq * (1.0f / 128.0f) - mu * mu;
        float rs = rsqrtf(fmaxf(var, 0.0f) + EPS);
        uint4* srow = (uint4*)(stg + tid * 272);
        #pragma unroll
        for (int ch = 0; ch < 4; ch++) {
            uint32_t t[32];
            TC_LD_X32(t, tmem + TM_D + ch * 32);
            TC_WAIT_LD();
            uint32_t hp[16];
            #pragma unroll
            for (int c2 = 0; c2 < 16; c2++) {
                int c = ch * 32 + c2 * 2;
                float v0 = __uint_as_float(t[c2 * 2])     + sBias[c];
                float v1 = __uint_as_float(t[c2 * 2 + 1]) + sBias[c + 1];
                float o0 = fmaxf(sGam[c]     * (v0 - mu) * rs + sBet[c],     0.0f);
                float o1 = fmaxf(sGam[c + 1] * (v1 - mu) * rs + sBet[c + 1], 0.0f);
                __half2 h = __floats2half2_rn(o0, o1);
                hp[c2] = *(uint32_t*)&h;
            }
            srow[ch * 4 + 0] = make_uint4(hp[0],  hp[1],  hp[2],  hp[3]);
            srow[ch * 4 + 1] = make_uint4(hp[4],  hp[5],  hp[6],  hp[7]);
            srow[ch * 4 + 2] = make_uint4(hp[8],  hp[9],  hp[10], hp[11]);
            srow[ch * 4 + 3] = make_uint4(hp[12], hp[13], hp[14], hp[15]);
        }
    }
    __syncthreads();

    // coalesced copy staging -> global fp16
    #pragma unroll
    for (int i = 0; i < 8; i++) {
        int idx = tid + i * 256;          // 0..2047
        int r = idx >> 4, q = idx & 15;
        int gr = row0 + r;
        if (gr < N_NODES)
            ((uint4*)outh)[(size_t)gr * 16 + q] = ((uint4*)(stg + r * 272))[q];
    }
    __syncthreads();

    if (tid == 0) { MBAR_INVAL(sbase + OFF_MBAR0); }
    __syncthreads();
    if (wid == 0) { TC_DEALLOC(tmem, TMEM_COLS); }

#else
    // ---- SIMT fallback (generic sm_103 pass only; never selected at runtime) ----
    const float* wtrel  = d_wt + (2 * layer)     * HID * HID;
    const float* wtroot = d_wt + (2 * layer + 1) * HID * HID;
    char* smem = smem_raw;
    float (*As)[132] = (float(*)[132])(smem);
    float (*Bs)[128] = (float(*)[128])(smem + 32 * 132 * 4);
    int lane = tid & 31;
    int w = tid >> 5;
    int w16 = w * 16;

    float acc[16][4];
    #pragma unroll
    for (int r = 0; r < 16; r++)
        #pragma unroll
        for (int j = 0; j < 4; j++) acc[r][j] = 0.0f;

    #pragma unroll
    for (int pass = 0; pass < 2; pass++) {
        const __half* A = pass ? d_xh : d_aggh;
        const float* Wt = pass ? wtroot : wtrel;
        #pragma unroll
        for (int k0 = 0; k0 < 128; k0 += 32) {
            __syncthreads();
            #pragma unroll
            for (int i = 0; i < 16; i++) {
                int r = w + i * 8;
                int gr = row0 + r;
                As[lane][r] = (gr < N_NODES)
                    ? __half2float(A[(size_t)gr * HID + k0 + lane]) : 0.0f;
            }
            #pragma unroll
            for (int i = 0; i < 16; i++) {
                int idx = tid + i * 256;
                int kk = idx >> 7, nn = idx & 127;
                Bs[kk][nn] = Wt[(size_t)nn * HID + k0 + kk];
            }
            __syncthreads();
            #pragma unroll
            for (int kc = 0; kc < 32; kc++) {
                float4 b4 = *(const float4*)&Bs[kc][lane * 4];
                float ar[16];
                *(float4*)&ar[0]  = *(const float4*)&As[kc][w16];
                *(float4*)&ar[4]  = *(const float4*)&As[kc][w16 + 4];
                *(float4*)&ar[8]  = *(const float4*)&As[kc][w16 + 8];
                *(float4*)&ar[12] = *(const float4*)&As[kc][w16 + 12];
                #pragma unroll
                for (int r = 0; r < 16; r++) {
                    acc[r][0] += ar[r] * b4.x;
                    acc[r][1] += ar[r] * b4.y;
                    acc[r][2] += ar[r] * b4.z;
                    acc[r][3] += ar[r] * b4.w;
                }
            }
        }
    }

    int c0 = lane * 4;
    float4 bb = *(const float4*)&brel[c0];
    float4 gg = *(const float4*)&gam[c0];
    float4 be = *(const float4*)&bet[c0];
    #pragma unroll
    for (int r = 0; r < 16; r++) {
        int gr = row0 + w16 + r;
        if (gr >= N_NODES) break;
        float v0 = acc[r][0] + bb.x, v1 = acc[r][1] + bb.y;
        float v2 = acc[r][2] + bb.z, v3 = acc[r][3] + bb.w;
        float mu = warp_sum(v0 + v1 + v2 + v3) * (1.0f / 128.0f);
        float dd0 = v0 - mu, dd1 = v1 - mu, dd2 = v2 - mu, dd3 = v3 - mu;
        float var = warp_sum(dd0 * dd0 + dd1 * dd1 + dd2 * dd2 + dd3 * dd3) * (1.0f / 128.0f);
        float rsq = rsqrtf(var + EPS);
        float o0 = fmaxf(gg.x * dd0 * rsq + be.x, 0.0f);
        float o1 = fmaxf(gg.y * dd1 * rsq + be.y, 0.0f);
        float o2 = fmaxf(gg.z * dd2 * rsq + be.z, 0.0f);
        float o3 = fmaxf(gg.w * dd3 * rsq + be.w, 0.0f);
        __half2 h0 = __floats2half2_rn(o0, o1);
        __half2 h1 = __floats2half2_rn(o2, o3);
        ((uint2*)outh)[(size_t)gr * 32 + lane] =
            make_uint2(*(uint32_t*)&h0, *(uint32_t*)&h1);
    }
#endif
}

// -------- graph mean pooling: fp16 source, run-length atomics --------
__global__ void pool_kernel(const void* __restrict__ batch) {
    int warp = (blockIdx.x * blockDim.x + threadIdx.x) >> 5;
    int lane = threadIdx.x & 31;
    int r0 = warp * 32;
    if (r0 >= N_NODES) return;
    int rend = r0 + 32; if (rend > N_NODES) rend = N_NODES;
    int curg = -1, cnt = 0;
    float p0 = 0.f, p1 = 0.f, p2 = 0.f, p3 = 0.f;
    for (int r = r0; r < rend; r++) {
        int g = load_idx(batch, r);
        uint2 u = ((const uint2*)d_yh)[(size_t)r * 32 + lane];
        float2 f0 = __half22float2(*(__half2*)&u.x);
        float2 f1 = __half22float2(*(__half2*)&u.y);
        if (g != curg) {
            if (curg >= 0) {
                float* pp = &d_pooled[curg * HID + lane * 4];
                atomicAdd(pp + 0, p0); atomicAdd(pp + 1, p1);
                atomicAdd(pp + 2, p2); atomicAdd(pp + 3, p3);
                if (lane == 0) atomicAdd(&d_cnt[curg], (float)cnt);
            }
            curg = g; cnt = 1; p0 = f0.x; p1 = f0.y; p2 = f1.x; p3 = f1.y;
        } else { p0 += f0.x; p1 += f0.y; p2 += f1.x; p3 += f1.y; cnt++; }
    }
    if (curg >= 0) {
        float* pp = &d_pooled[curg * HID + lane * 4];
        atomicAdd(pp + 0, p0); atomicAdd(pp + 1, p1);
        atomicAdd(pp + 2, p2); atomicAdd(pp + 3, p3);
        if (lane == 0) atomicAdd(&d_cnt[curg], (float)cnt);
    }
}

__global__ void cls_kernel(const float* __restrict__ Wc, const float* __restrict__ bc,
                           float* __restrict__ out) {
    int g = blockIdx.x;
    int o = threadIdx.x >> 5, lane = threadIdx.x & 31;
    if (o >= OUTD) return;
    float inv = 1.0f / fmaxf(d_cnt[g], 1.0f);
    float s = 0.0f;
    for (int k = lane; k < HID; k += 32)
        s += d_pooled[g * HID + k] * Wc[k * OUTD + o];
    s = warp_sum(s);
    if (lane == 0) out[g * OUTD + o] = s * inv + bc[o];
}

extern "C" void kernel_launch(void* const* d_in, const int* in_sizes, int n_in,
                              void* d_out, int out_size) {
    const float* x      = (const float*)d_in[0];
    const void*  ei     = d_in[1];
    const void*  batch  = d_in[2];
    const float* W_rel  = (const float*)d_in[3];
    const float* b_rel  = (const float*)d_in[4];
    const float* W_root = (const float*)d_in[5];
    const float* gamma  = (const float*)d_in[6];
    const float* beta   = (const float*)d_in[7];
    const float* Wc     = (const float*)d_in[8];
    const float* bc     = (const float*)d_in[9];
    float* out = (float*)d_out;

    cudaFuncSetAttribute(layer_tc, cudaFuncAttributeMaxDynamicSharedMemorySize, SMEM_TOTAL);

    prep_kernel<<<485 + 6250, 256>>>(ei, W_rel, W_root, x);
    count_kernel<<<(N_EDGES / 2 + 255) / 256, 256>>>(ei);
    scanA_kernel<<<SCAN_BLOCKS, 1024>>>();
    scanB_kernel<<<SCAN_BLOCKS, 1024>>>();
    fill_kernel<<<(N_EDGES / 2 + 255) / 256, 256>>>(ei);

    int ntiles = (N_NODES + 127) / 128;
    // layer 0: gather d_xh -> d_aggh; GEMM(A=d_aggh,d_xh) -> writes d_xh
    aggregate_kernel<<<N_NODES / 8, 256>>>();
    layer_tc<<<ntiles, 256, SMEM_TOTAL>>>(b_rel, gamma, beta, 0, 0);
    // layer 1: gather d_xh -> d_aggh; GEMM -> writes d_yh
    aggregate_kernel<<<N_NODES / 8, 256>>>();
    layer_tc<<<ntiles, 256, SMEM_TOTAL>>>(b_rel + HID, gamma + HID, beta + HID, 1, 1);

    pool_kernel<<<196, 256>>>(batch);
    cls_kernel<<<NG, 320>>>(Wc, bc, out);
}